// round 2
// baseline (speedup 1.0000x reference)
#include <cuda_runtime.h>

// Problem constants
#define BB 16
#define CC 96
#define HH 128
#define WW 128
#define HWSZ (HH*WW)

// Scratch (allocation-guard-safe: __device__ globals)
__device__ float g_flow [BB*2  *HWSZ];
__device__ float g_feat2[BB*CC *HWSZ];
__device__ float g_corr [BB*49 *HWSZ];
__device__ float g_x1   [BB*128*HWSZ];
__device__ float g_x2   [BB*64 *HWSZ];
__device__ float g_x3   [BB*32 *HWSZ];

__device__ __forceinline__ float lrelu_f(float x) { return x >= 0.f ? x : 0.1f * x; }

// ---------------------------------------------------------------------------
// 1) upflow: transposed conv, stride 2, k=4, depthwise (2 groups), pad 2
// ---------------------------------------------------------------------------
__global__ void upflow_kernel(const float* __restrict__ flow,
                              const float* __restrict__ wu) {
    int idx = blockIdx.x * blockDim.x + threadIdx.x;
    if (idx >= BB*2*HWSZ) return;
    int ox = idx & 127;
    int oy = (idx >> 7) & 127;
    int ch = (idx >> 14) & 1;
    int b  = idx >> 15;
    float acc = 0.f;
    #pragma unroll
    for (int ky = 0; ky < 4; ky++) {
        int jy = oy + ky - 2;
        if (jy < 0 || jy > 126 || (jy & 1)) continue;
        int iy = jy >> 1;
        #pragma unroll
        for (int kx = 0; kx < 4; kx++) {
            int jx = ox + kx - 2;
            if (jx < 0 || jx > 126 || (jx & 1)) continue;
            int ix = jx >> 1;
            acc += wu[ch*16 + (3-ky)*4 + (3-kx)] *
                   flow[((b*2 + ch)*64 + iy)*64 + ix];
        }
    }
    g_flow[idx] = acc;
}

// ---------------------------------------------------------------------------
// 2) backward warp with zero padding + validity mask
// ---------------------------------------------------------------------------
__global__ void warp_kernel(const float* __restrict__ feat) {
    int idx = blockIdx.x * blockDim.x + threadIdx.x;
    if (idx >= BB*HWSZ) return;
    int x = idx & 127;
    int y = (idx >> 7) & 127;
    int b = idx >> 14;

    float fx = 2.5f * g_flow[(b*2 + 0)*HWSZ + y*WW + x];
    float fy = 2.5f * g_flow[(b*2 + 1)*HWSZ + y*WW + x];
    float sx = (float)x + fx;
    float sy = (float)y + fy;
    float x0f = floorf(sx), y0f = floorf(sy);
    float x1f = x0f + 1.f, y1f = y0f + 1.f;

    float wa = (x1f - sx) * (y1f - sy);
    float wb = (sx - x0f) * (y1f - sy);
    float wc = (x1f - sx) * (sy - y0f);
    float wd = (sx - x0f) * (sy - y0f);

    bool vx0 = (x0f >= 0.f) && (x0f <= 127.f);
    bool vx1 = (x1f >= 0.f) && (x1f <= 127.f);
    bool vy0 = (y0f >= 0.f) && (y0f <= 127.f);
    bool vy1 = (y1f >= 0.f) && (y1f <= 127.f);

    float ma = (vx0 && vy0) ? wa : 0.f;
    float mb = (vx1 && vy0) ? wb : 0.f;
    float mc = (vx0 && vy1) ? wc : 0.f;
    float md = (vx1 && vy1) ? wd : 0.f;
    float maskval = ma + mb + mc + md;

    int ix0 = min(max((int)x0f, 0), 127);
    int ix1 = min(max((int)x1f, 0), 127);
    int iy0 = min(max((int)y0f, 0), 127);
    int iy1 = min(max((int)y1f, 0), 127);

    int base = b * CC * HWSZ;
    int po = y*WW + x;
    if (maskval > 0.999f) {
        int oa = iy0*WW + ix0, ob = iy0*WW + ix1;
        int oc = iy1*WW + ix0, od = iy1*WW + ix1;
        for (int c = 0; c < CC; c++) {
            const float* img = feat + base + c*HWSZ;
            float v = ma*img[oa] + mb*img[ob] + mc*img[oc] + md*img[od];
            g_feat2[base + c*HWSZ + po] = v;
        }
    } else {
        for (int c = 0; c < CC; c++)
            g_feat2[base + c*HWSZ + po] = 0.f;
    }
}

// ---------------------------------------------------------------------------
// 3) correlation (49 displacements, mean over 96 ch) + lrelu
// ---------------------------------------------------------------------------
__global__ __launch_bounds__(256)
void corr_kernel(const float* __restrict__ first) {
    __shared__ float sS[22][24];
    int tx = threadIdx.x, ty = threadIdx.y;
    int x0 = blockIdx.x * 16, y0 = blockIdx.y * 16;
    int b  = blockIdx.z;
    int x = x0 + tx, y = y0 + ty;
    int tid = ty*16 + tx;

    float acc[49];
    #pragma unroll
    for (int d = 0; d < 49; d++) acc[d] = 0.f;

    for (int c = 0; c < CC; c++) {
        const float* sp = g_feat2 + (b*CC + c)*HWSZ;
        for (int i = tid; i < 22*22; i += 256) {
            int r = i / 22, cc2 = i % 22;
            int yy = y0 - 3 + r, xx = x0 - 3 + cc2;
            float v = 0.f;
            if (yy >= 0 && yy < HH && xx >= 0 && xx < WW) v = sp[yy*WW + xx];
            sS[r][cc2] = v;
        }
        __syncthreads();
        float f = first[(b*CC + c)*HWSZ + y*WW + x];
        #pragma unroll
        for (int dy = 0; dy < 7; dy++)
            #pragma unroll
            for (int dx = 0; dx < 7; dx++)
                acc[dy*7 + dx] += f * sS[ty + dy][tx + dx];
        __syncthreads();
    }
    const float inv = 1.f / 96.f;
    #pragma unroll
    for (int d = 0; d < 49; d++)
        g_corr[(b*49 + d)*HWSZ + y*WW + x] = lrelu_f(acc[d] * inv);
}

// ---------------------------------------------------------------------------
// 4) direct conv, register-tiled v2:
//    tile 64(x) x 32(y), block (64,4) = 256 thr, each thread 8 px x OCB oc.
//    Weights staged in 32-ic chunks; input staged 2 ic per barrier pair.
//    LDS/FFMA = 0.25 (was 0.375).
// ---------------------------------------------------------------------------
template<int IC, int OC, int OCB, int K, int PAD, bool RELU, bool ADDFLOW>
__global__ __launch_bounds__(256, 2)
void conv_kernel(const float* __restrict__ in, const float* __restrict__ wt,
                 const float* __restrict__ bias, float* __restrict__ out) {
    constexpr int TX = 64, TY = 32;
    constexpr int TSX = TX + 2*PAD;          // input tile width
    constexpr int TSY = TY + 2*PAD;          // input tile height
    constexpr int TSXP = TSX + 2;            // padded row stride
    constexpr int WCH = (IC < 32) ? IC : 32; // ic chunk for weights
    constexpr int WST = WCH * K * K;         // per-oc weight stride in smem

    __shared__ float sW[OCB * WST];
    __shared__ float sIn[2][TSY][TSXP];

    int tx = threadIdx.x;            // 0..63
    int ty = threadIdx.y;            // 0..3
    int tid = ty*64 + tx;
    int x0 = blockIdx.x * TX, y0 = blockIdx.y * TY;
    int zc = blockIdx.z;
    int ocg = zc % (OC / OCB);
    int b   = zc / (OC / OCB);
    int oc0 = ocg * OCB;

    float acc[8][OCB];
    #pragma unroll
    for (int r = 0; r < 8; r++)
        #pragma unroll
        for (int o = 0; o < OCB; o++) acc[r][o] = 0.f;

    for (int ic0 = 0; ic0 < IC; ic0 += WCH) {
        const int icc = (IC - ic0 < WCH) ? (IC - ic0) : WCH;
        __syncthreads();   // protect sW against readers from previous chunk
        // stage weight chunk: sW[o*WST + icl*K*K + t]
        for (int i = tid; i < OCB * icc * K * K; i += 256) {
            int o   = i / (icc * K * K);
            int rem = i - o * (icc * K * K);
            int icl = rem / (K * K);
            int t   = rem - icl * (K * K);
            sW[o*WST + icl*K*K + t] =
                wt[((oc0 + o)*IC + ic0 + icl)*(K*K) + t];
        }

        for (int icl = 0; icl < icc; icl += 2) {
            const int n2 = (icc - icl < 2) ? (icc - icl) : 2;
            __syncthreads();
            // stage up to 2 input channels
            for (int j = 0; j < n2; j++) {
                const float* ip = in + (b*IC + ic0 + icl + j)*HWSZ;
                for (int i = tid; i < TSY*TSX; i += 256) {
                    int r  = i / TSX;
                    int cc = i - r * TSX;
                    int yy = y0 - PAD + r, xx = x0 - PAD + cc;
                    sIn[j][r][cc] = (yy >= 0 && yy < HH && xx >= 0 && xx < WW)
                                    ? ip[yy*WW + xx] : 0.f;
                }
            }
            __syncthreads();

            for (int j = 0; j < n2; j++) {
                const float* wp = sW + (icl + j)*K*K;
                #pragma unroll
                for (int t = 0; t < K*K; t++) {
                    int ky = t / K, kx = t - ky*K;
                    float v[8];
                    #pragma unroll
                    for (int r = 0; r < 8; r++)
                        v[r] = sIn[j][ty + 4*r + ky][tx + kx];
                    #pragma unroll
                    for (int o = 0; o < OCB; o++) {
                        float wv = wp[o*WST + t];
                        #pragma unroll
                        for (int r = 0; r < 8; r++)
                            acc[r][o] = fmaf(v[r], wv, acc[r][o]);
                    }
                }
            }
        }
    }

    #pragma unroll
    for (int o = 0; o < OCB; o++) {
        float bv = bias[oc0 + o];
        #pragma unroll
        for (int r = 0; r < 8; r++) {
            int y = y0 + ty + 4*r, x = x0 + tx;
            float val = acc[r][o] + bv;
            if (RELU) val = lrelu_f(val);
            if (ADDFLOW) val += g_flow[(b*2 + oc0 + o)*HWSZ + y*WW + x];
            out[(b*OC + oc0 + o)*HWSZ + y*WW + x] = val;
        }
    }
}

// ---------------------------------------------------------------------------
// launch
// ---------------------------------------------------------------------------
extern "C" void kernel_launch(void* const* d_in, const int* in_sizes, int n_in,
                              void* d_out, int out_size) {
    const float* featFirst  = (const float*)d_in[2];
    const float* featSecond = (const float*)d_in[3];
    const float* tensorFlow = (const float*)d_in[4];
    const float* wu = (const float*)d_in[5];
    const float* w1 = (const float*)d_in[6];
    const float* b1 = (const float*)d_in[7];
    const float* w2 = (const float*)d_in[8];
    const float* b2 = (const float*)d_in[9];
    const float* w3 = (const float*)d_in[10];
    const float* b3 = (const float*)d_in[11];
    const float* w4 = (const float*)d_in[12];
    const float* b4 = (const float*)d_in[13];
    float* out = (float*)d_out;

    float *gflow, *gfeat2, *gcorr, *gx1, *gx2, *gx3;
    cudaGetSymbolAddress((void**)&gflow,  g_flow);
    cudaGetSymbolAddress((void**)&gfeat2, g_feat2);
    cudaGetSymbolAddress((void**)&gcorr,  g_corr);
    cudaGetSymbolAddress((void**)&gx1,    g_x1);
    cudaGetSymbolAddress((void**)&gx2,    g_x2);
    cudaGetSymbolAddress((void**)&gx3,    g_x3);

    upflow_kernel<<<(BB*2*HWSZ + 255)/256, 256>>>(tensorFlow, wu);
    warp_kernel<<<(BB*HWSZ + 255)/256, 256>>>(featSecond);
    corr_kernel<<<dim3(WW/16, HH/16, BB), dim3(16,16)>>>(featFirst);

    conv_kernel<49, 128, 8, 3, 1, true,  false>
        <<<dim3(WW/64, HH/32, BB*(128/8)), dim3(64,4)>>>(gcorr, w1, b1, gx1);
    conv_kernel<128, 64, 8, 3, 1, true,  false>
        <<<dim3(WW/64, HH/32, BB*(64/8)),  dim3(64,4)>>>(gx1, w2, b2, gx2);
    conv_kernel<64,  32, 8, 3, 1, true,  false>
        <<<dim3(WW/64, HH/32, BB*(32/8)),  dim3(64,4)>>>(gx2, w3, b3, gx3);
    conv_kernel<32,   2, 2, 5, 2, false, true>
        <<<dim3(WW/64, HH/32, BB*(2/2)),   dim3(64,4)>>>(gx3, w4, b4, out);
}

// round 3
// speedup vs baseline: 1.7026x; 1.7026x over previous
#include <cuda_runtime.h>

// Problem constants
#define BB 16
#define CC 96
#define HH 128
#define WW 128
#define HWSZ (HH*WW)

// Scratch (allocation-guard-safe: __device__ globals)
__device__ float g_flow [BB*2  *HWSZ];
__device__ float g_feat2[BB*CC *HWSZ];
__device__ float g_corr [BB*49 *HWSZ];
__device__ float g_x1   [BB*128*HWSZ];
__device__ float g_x2   [BB*64 *HWSZ];
__device__ float g_x3   [BB*32 *HWSZ];

__device__ __forceinline__ float lrelu_f(float x) { return x >= 0.f ? x : 0.1f * x; }

// ---------------------------------------------------------------------------
// 1) upflow: transposed conv, stride 2, k=4, depthwise (2 groups), pad 2
// ---------------------------------------------------------------------------
__global__ void upflow_kernel(const float* __restrict__ flow,
                              const float* __restrict__ wu) {
    int idx = blockIdx.x * blockDim.x + threadIdx.x;
    if (idx >= BB*2*HWSZ) return;
    int ox = idx & 127;
    int oy = (idx >> 7) & 127;
    int ch = (idx >> 14) & 1;
    int b  = idx >> 15;
    float acc = 0.f;
    #pragma unroll
    for (int ky = 0; ky < 4; ky++) {
        int jy = oy + ky - 2;
        if (jy < 0 || jy > 126 || (jy & 1)) continue;
        int iy = jy >> 1;
        #pragma unroll
        for (int kx = 0; kx < 4; kx++) {
            int jx = ox + kx - 2;
            if (jx < 0 || jx > 126 || (jx & 1)) continue;
            int ix = jx >> 1;
            acc += wu[ch*16 + (3-ky)*4 + (3-kx)] *
                   flow[((b*2 + ch)*64 + iy)*64 + ix];
        }
    }
    g_flow[idx] = acc;
}

// ---------------------------------------------------------------------------
// 2) backward warp with zero padding + validity mask
// ---------------------------------------------------------------------------
__global__ void warp_kernel(const float* __restrict__ feat) {
    int idx = blockIdx.x * blockDim.x + threadIdx.x;
    if (idx >= BB*HWSZ) return;
    int x = idx & 127;
    int y = (idx >> 7) & 127;
    int b = idx >> 14;

    float fx = 2.5f * g_flow[(b*2 + 0)*HWSZ + y*WW + x];
    float fy = 2.5f * g_flow[(b*2 + 1)*HWSZ + y*WW + x];
    float sx = (float)x + fx;
    float sy = (float)y + fy;
    float x0f = floorf(sx), y0f = floorf(sy);
    float x1f = x0f + 1.f, y1f = y0f + 1.f;

    float wa = (x1f - sx) * (y1f - sy);
    float wb = (sx - x0f) * (y1f - sy);
    float wc = (x1f - sx) * (sy - y0f);
    float wd = (sx - x0f) * (sy - y0f);

    bool vx0 = (x0f >= 0.f) && (x0f <= 127.f);
    bool vx1 = (x1f >= 0.f) && (x1f <= 127.f);
    bool vy0 = (y0f >= 0.f) && (y0f <= 127.f);
    bool vy1 = (y1f >= 0.f) && (y1f <= 127.f);

    float ma = (vx0 && vy0) ? wa : 0.f;
    float mb = (vx1 && vy0) ? wb : 0.f;
    float mc = (vx0 && vy1) ? wc : 0.f;
    float md = (vx1 && vy1) ? wd : 0.f;
    float maskval = ma + mb + mc + md;

    int ix0 = min(max((int)x0f, 0), 127);
    int ix1 = min(max((int)x1f, 0), 127);
    int iy0 = min(max((int)y0f, 0), 127);
    int iy1 = min(max((int)y1f, 0), 127);

    int base = b * CC * HWSZ;
    int po = y*WW + x;
    if (maskval > 0.999f) {
        int oa = iy0*WW + ix0, ob = iy0*WW + ix1;
        int oc = iy1*WW + ix0, od = iy1*WW + ix1;
        for (int c = 0; c < CC; c++) {
            const float* img = feat + base + c*HWSZ;
            float v = ma*img[oa] + mb*img[ob] + mc*img[oc] + md*img[od];
            g_feat2[base + c*HWSZ + po] = v;
        }
    } else {
        for (int c = 0; c < CC; c++)
            g_feat2[base + c*HWSZ + po] = 0.f;
    }
}

// ---------------------------------------------------------------------------
// 3) correlation (49 displacements, mean over 96 ch) + lrelu
// ---------------------------------------------------------------------------
__global__ __launch_bounds__(256)
void corr_kernel(const float* __restrict__ first) {
    __shared__ float sS[22][24];
    int tx = threadIdx.x, ty = threadIdx.y;
    int x0 = blockIdx.x * 16, y0 = blockIdx.y * 16;
    int b  = blockIdx.z;
    int x = x0 + tx, y = y0 + ty;
    int tid = ty*16 + tx;

    float acc[49];
    #pragma unroll
    for (int d = 0; d < 49; d++) acc[d] = 0.f;

    for (int c = 0; c < CC; c++) {
        const float* sp = g_feat2 + (b*CC + c)*HWSZ;
        for (int i = tid; i < 22*22; i += 256) {
            int r = i / 22, cc2 = i % 22;
            int yy = y0 - 3 + r, xx = x0 - 3 + cc2;
            float v = 0.f;
            if (yy >= 0 && yy < HH && xx >= 0 && xx < WW) v = sp[yy*WW + xx];
            sS[r][cc2] = v;
        }
        __syncthreads();
        float f = first[(b*CC + c)*HWSZ + y*WW + x];
        #pragma unroll
        for (int dy = 0; dy < 7; dy++)
            #pragma unroll
            for (int dx = 0; dx < 7; dx++)
                acc[dy*7 + dx] += f * sS[ty + dy][tx + dx];
        __syncthreads();
    }
    const float inv = 1.f / 96.f;
    #pragma unroll
    for (int d = 0; d < 49; d++)
        g_corr[(b*49 + d)*HWSZ + y*WW + x] = lrelu_f(acc[d] * inv);
}

// ---------------------------------------------------------------------------
// 4) direct conv v3: 32x32 tile, block (8,32), thread = 4 consecutive x px
//    x OCB oc. Vectorized LDS (float4 values + float4 weight broadcasts),
//    weights fully pre-staged transposed [ic][tap][oc], input double-buffered
//    (1 barrier per ic). Regs capped at 64 (4 CTAs/SM).
// ---------------------------------------------------------------------------
template<int IC, int OC, int OCB, int K, int PAD, bool RELU, bool ADDFLOW>
__global__ __launch_bounds__(256, 4)
void conv_kernel(const float* __restrict__ in, const float* __restrict__ wt,
                 const float* __restrict__ bias, float* __restrict__ out) {
    constexpr int TX = 32, TY = 32;
    constexpr int TSX = TX + 2*PAD;
    constexpr int TSY = TY + 2*PAD;
    constexpr int TSXP = (TSX + 3) & ~3;      // 16B-aligned row stride

    __shared__ float sW[IC * K * K * OCB];
    __shared__ float sIn[2][TSY][TSXP];

    const int tx = threadIdx.x;   // 0..7  (x-quad)
    const int ty = threadIdx.y;   // 0..31 (y row)
    const int tid = ty*8 + tx;
    const int x0 = blockIdx.x * TX, y0 = blockIdx.y * TY;
    const int zc = blockIdx.z;
    const int ocg = zc % (OC / OCB);
    const int b   = zc / (OC / OCB);
    const int oc0 = ocg * OCB;

    // stage all weights for this oc-group, transposed: sW[(ic*K*K + t)*OCB + o]
    for (int i = tid; i < IC*K*K*OCB; i += 256) {
        int o   = i % OCB;
        int rst = i / OCB;
        int t   = rst % (K*K);
        int ic  = rst / (K*K);
        sW[i] = wt[((oc0 + o)*IC + ic)*(K*K) + t];
    }

    // stage input channel `ic` into buffer p
    auto stage = [&](int ic, int p) {
        const float* ip = in + (b*IC + ic)*HWSZ;
        #pragma unroll 2
        for (int i = tid; i < TSY*TSX; i += 256) {
            int r  = i / TSX;
            int c  = i - r*TSX;
            int yy = y0 - PAD + r, xx = x0 - PAD + c;
            sIn[p][r][c] = (yy >= 0 && yy < HH && xx >= 0 && xx < WW)
                           ? ip[yy*WW + xx] : 0.f;
        }
    };

    stage(0, 0);
    __syncthreads();

    float acc[OCB][4];
    #pragma unroll
    for (int o = 0; o < OCB; o++)
        #pragma unroll
        for (int i = 0; i < 4; i++) acc[o][i] = 0.f;

    for (int ic = 0; ic < IC; ic++) {
        const int p = ic & 1;
        if (ic + 1 < IC) stage(ic + 1, p ^ 1);

        const float* wp = sW + ic*(K*K*OCB);
        #pragma unroll
        for (int ky = 0; ky < K; ky++) {
            const float* rowp = &sIn[p][ty + ky][tx*4];
            float4 Af = *(const float4*)rowp;
            float4 Bf = *(const float4*)(rowp + 4);
            float va[8] = {Af.x, Af.y, Af.z, Af.w, Bf.x, Bf.y, Bf.z, Bf.w};
            #pragma unroll
            for (int kx = 0; kx < K; kx++) {
                const float* wq = wp + (ky*K + kx)*OCB;
                float wv[OCB];
                if constexpr (OCB % 4 == 0) {
                    #pragma unroll
                    for (int j = 0; j < OCB/4; j++) {
                        float4 w4 = *(const float4*)(wq + 4*j);
                        wv[4*j+0] = w4.x; wv[4*j+1] = w4.y;
                        wv[4*j+2] = w4.z; wv[4*j+3] = w4.w;
                    }
                } else {
                    #pragma unroll
                    for (int o = 0; o < OCB; o++) wv[o] = wq[o];
                }
                #pragma unroll
                for (int o = 0; o < OCB; o++)
                    #pragma unroll
                    for (int i = 0; i < 4; i++)
                        acc[o][i] = fmaf(va[i + kx], wv[o], acc[o][i]);
            }
        }
        __syncthreads();
    }

    // epilogue: float4 stores (x0 + tx*4 is 16B aligned)
    const int y = y0 + ty;
    const int x = x0 + tx*4;
    #pragma unroll
    for (int o = 0; o < OCB; o++) {
        float bv = bias[oc0 + o];
        float4 r4;
        r4.x = acc[o][0] + bv; r4.y = acc[o][1] + bv;
        r4.z = acc[o][2] + bv; r4.w = acc[o][3] + bv;
        if (RELU) {
            r4.x = lrelu_f(r4.x); r4.y = lrelu_f(r4.y);
            r4.z = lrelu_f(r4.z); r4.w = lrelu_f(r4.w);
        }
        if (ADDFLOW) {
            float4 f4 = *(const float4*)&g_flow[(b*2 + oc0 + o)*HWSZ + y*WW + x];
            r4.x += f4.x; r4.y += f4.y; r4.z += f4.z; r4.w += f4.w;
        }
        *(float4*)&out[(b*OC + oc0 + o)*HWSZ + y*WW + x] = r4;
    }
}

// ---------------------------------------------------------------------------
// launch
// ---------------------------------------------------------------------------
extern "C" void kernel_launch(void* const* d_in, const int* in_sizes, int n_in,
                              void* d_out, int out_size) {
    const float* featFirst  = (const float*)d_in[2];
    const float* featSecond = (const float*)d_in[3];
    const float* tensorFlow = (const float*)d_in[4];
    const float* wu = (const float*)d_in[5];
    const float* w1 = (const float*)d_in[6];
    const float* b1 = (const float*)d_in[7];
    const float* w2 = (const float*)d_in[8];
    const float* b2 = (const float*)d_in[9];
    const float* w3 = (const float*)d_in[10];
    const float* b3 = (const float*)d_in[11];
    const float* w4 = (const float*)d_in[12];
    const float* b4 = (const float*)d_in[13];
    float* out = (float*)d_out;

    float *gflow, *gfeat2, *gcorr, *gx1, *gx2, *gx3;
    cudaGetSymbolAddress((void**)&gflow,  g_flow);
    cudaGetSymbolAddress((void**)&gfeat2, g_feat2);
    cudaGetSymbolAddress((void**)&gcorr,  g_corr);
    cudaGetSymbolAddress((void**)&gx1,    g_x1);
    cudaGetSymbolAddress((void**)&gx2,    g_x2);
    cudaGetSymbolAddress((void**)&gx3,    g_x3);

    upflow_kernel<<<(BB*2*HWSZ + 255)/256, 256>>>(tensorFlow, wu);
    warp_kernel<<<(BB*HWSZ + 255)/256, 256>>>(featSecond);
    corr_kernel<<<dim3(WW/16, HH/16, BB), dim3(16,16)>>>(featFirst);

    conv_kernel<49, 128, 8, 3, 1, true,  false>
        <<<dim3(WW/32, HH/32, BB*(128/8)), dim3(8,32)>>>(gcorr, w1, b1, gx1);
    conv_kernel<128, 64, 8, 3, 1, true,  false>
        <<<dim3(WW/32, HH/32, BB*(64/8)),  dim3(8,32)>>>(gx1, w2, b2, gx2);
    conv_kernel<64,  32, 8, 3, 1, true,  false>
        <<<dim3(WW/32, HH/32, BB*(32/8)),  dim3(8,32)>>>(gx2, w3, b3, gx3);
    conv_kernel<32,   2, 2, 5, 2, false, true>
        <<<dim3(WW/32, HH/32, BB*(2/2)),   dim3(8,32)>>>(gx3, w4, b4, out);
}